// round 14
// baseline (speedup 1.0000x reference)
#include <cuda_runtime.h>
#include <cuda_bf16.h>
#include <cuda_fp16.h>
#include <cuda_fp8.h>
#include <cstdint>

constexpr int B = 4;
constexpr int S = 4096;
constexpr int D = 256;
constexpr int L = 8921;

constexpr int NST = 32;     // S/128 s-tiles in K1
constexpr int NLT = 70;     // ceil(L/128)

// ---------------- device scratch ------------------------------------------
__device__ float g_pm[(size_t)B * L * NST];
__device__ float g_pz[(size_t)B * L * NST];
__device__ float g_M [(size_t)B * L];
__device__ float g_Zi[(size_t)B * L];

__device__ __half   gUh[(size_t)L * D];          // U fp16 hi
__device__ uint8_t  gA8[(size_t)L * D * 2];      // per k16 group: [uh8(16B) | ul8*2^12(16B)]
__device__ __half   gXh[(size_t)B * S * D];      // x fp16 hi (natural)
__device__ uint8_t  gB8[(size_t)B * S * D * 2];  // per k16 group: [xl8*2^12 | xh8]
__device__ __half   gVh[(size_t)B * D * S];      // x^T fp16 hi (for K3)
__device__ __half   gVl[(size_t)B * D * S];      // x^T fp16 lo

// ---------------- helpers --------------------------------------------------
__device__ __forceinline__ uint32_t smem_u32(const void* p) {
    uint32_t a;
    asm("{ .reg .u64 t; cvta.to.shared.u64 t, %1; cvt.u32.u64 %0, t; }" : "=r"(a) : "l"(p));
    return a;
}
__device__ __forceinline__ void cp16(uint32_t d, const void* s, uint32_t sz) {
    asm volatile("cp.async.cg.shared.global [%0], [%1], 16, %2;"
                 :: "r"(d), "l"(s), "r"(sz) : "memory");
}
__device__ __forceinline__ void cp_commit() {
    asm volatile("cp.async.commit_group;" ::: "memory");
}
template<int N> __device__ __forceinline__ void cp_wait() {
    asm volatile("cp.async.wait_group %0;" :: "n"(N) : "memory");
}
__device__ __forceinline__ void ldsm4(uint32_t* r, uint32_t a) {
    asm volatile("ldmatrix.sync.aligned.m8n8.x4.shared.b16 {%0,%1,%2,%3}, [%4];"
                 : "=r"(r[0]), "=r"(r[1]), "=r"(r[2]), "=r"(r[3]) : "r"(a));
}
__device__ __forceinline__ void mma_f16(float* d, const uint32_t* a, uint32_t b0, uint32_t b1) {
    asm volatile("mma.sync.aligned.m16n8k16.row.col.f32.f16.f16.f32 "
                 "{%0,%1,%2,%3}, {%4,%5,%6,%7}, {%8,%9}, {%0,%1,%2,%3};"
                 : "+f"(d[0]), "+f"(d[1]), "+f"(d[2]), "+f"(d[3])
                 : "r"(a[0]), "r"(a[1]), "r"(a[2]), "r"(a[3]), "r"(b0), "r"(b1));
}
__device__ __forceinline__ void mma_fp8(float* d, const uint32_t* a, uint32_t b0, uint32_t b1) {
    asm volatile("mma.sync.aligned.m16n8k32.row.col.f32.e4m3.e4m3.f32 "
                 "{%0,%1,%2,%3}, {%4,%5,%6,%7}, {%8,%9}, {%0,%1,%2,%3};"
                 : "+f"(d[0]), "+f"(d[1]), "+f"(d[2]), "+f"(d[3])
                 : "r"(a[0]), "r"(a[1]), "r"(a[2]), "r"(a[3]), "r"(b0), "r"(b1));
}
__device__ __forceinline__ uint8_t to_e4m3(float f) {
    return (uint8_t)__nv_cvt_float_to_fp8(f, __NV_SATFINITE, __NV_E4M3);
}
__device__ __forceinline__ uint32_t packhh(__half a, __half b) {
    __half2 t = __halves2half2(a, b);
    return *reinterpret_cast<uint32_t*>(&t);
}
__device__ __forceinline__ uint32_t packh2(float a, float b) {
    __half2 t = __floats2half2_rn(a, b);
    return *reinterpret_cast<uint32_t*>(&t);
}

constexpr float SC8 = 1.0f / 4096.0f;   // 2^-12

// ---------------- smem layouts ----------------------------------------------
constexpr int PITCH  = 80;          // shared row pitch (<=64B data + pad)

// K1: CTA 128(m) x 128(n), k-chunk 32
constexpr int OFF_AH = 0;           // 128 * 80 fp16 hi
constexpr int OFF_A8 = 10240;       // 128 * 80 fp8 packed
constexpr int OFF_BH = 20480;       // 128 * 80 fp16 hi
constexpr int OFF_B8 = 30720;       // 128 * 80 fp8 packed
constexpr int STAGE1 = 40960;
constexpr int HDR    = 6144;
constexpr int SMEM1  = HDR + 3 * STAGE1;   // 129024

// K3: k-chunk 32, fp16, A single-term (unchanged from R13)
constexpr int ST3_A  = 0;
constexpr int ST3_BH = 10240;
constexpr int ST3_BL = 30720;
constexpr int STAGE3 = 51200;
constexpr int SMEM3  = HDR + 3 * STAGE3;   // 159744

constexpr int LDC = 132;            // K1 epilogue staging row stride (128+4)
constexpr int LDC3 = 264;           // K3 epilogue staging row stride

// ---------------- precompute kernels ---------------------------------------
__global__ void k_split_u(const float* __restrict__ src) {
    int i = blockIdx.x * blockDim.x + threadIdx.x;
    if (i >= L * D / 4) return;
    float4 v = ((const float4*)src)[i];
    __half h0 = __float2half(v.x), h1 = __float2half(v.y),
           h2 = __float2half(v.z), h3 = __float2half(v.w);
    float r0 = v.x - __half2float(h0), r1 = v.y - __half2float(h1),
          r2 = v.z - __half2float(h2), r3 = v.w - __half2float(h3);
    ((uint2*)gUh)[i] = make_uint2(packhh(h0, h1), packhh(h2, h3));

    int k4 = i * 4;
    int row = k4 / D, k = k4 % D;
    int g = k >> 4, o = k & 15;
    size_t base = (size_t)row * (D * 2) + g * 32 + o;
    uint32_t hi8 = (uint32_t)to_e4m3(__half2float(h0))
                 | ((uint32_t)to_e4m3(__half2float(h1)) << 8)
                 | ((uint32_t)to_e4m3(__half2float(h2)) << 16)
                 | ((uint32_t)to_e4m3(__half2float(h3)) << 24);
    uint32_t lo8 = (uint32_t)to_e4m3(r0 * 4096.f)
                 | ((uint32_t)to_e4m3(r1 * 4096.f) << 8)
                 | ((uint32_t)to_e4m3(r2 * 4096.f) << 16)
                 | ((uint32_t)to_e4m3(r3 * 4096.f) << 24);
    *(uint32_t*)(gA8 + base)      = hi8;   // [uh8 | ul8']
    *(uint32_t*)(gA8 + base + 16) = lo8;
}
__global__ void k_splitx(const float* __restrict__ src) {
    int i = blockIdx.x * blockDim.x + threadIdx.x;
    if (i >= B * S * D / 4) return;
    float4 v = ((const float4*)src)[i];
    __half h0 = __float2half(v.x), h1 = __float2half(v.y),
           h2 = __float2half(v.z), h3 = __float2half(v.w);
    float r0 = v.x - __half2float(h0), r1 = v.y - __half2float(h1),
          r2 = v.z - __half2float(h2), r3 = v.w - __half2float(h3);
    ((uint2*)gXh)[i] = make_uint2(packhh(h0, h1), packhh(h2, h3));

    int k4 = i * 4;
    int row = k4 / D, k = k4 % D;
    int g = k >> 4, o = k & 15;
    size_t base = (size_t)row * (D * 2) + g * 32 + o;
    uint32_t hi8 = (uint32_t)to_e4m3(__half2float(h0))
                 | ((uint32_t)to_e4m3(__half2float(h1)) << 8)
                 | ((uint32_t)to_e4m3(__half2float(h2)) << 16)
                 | ((uint32_t)to_e4m3(__half2float(h3)) << 24);
    uint32_t lo8 = (uint32_t)to_e4m3(r0 * 4096.f)
                 | ((uint32_t)to_e4m3(r1 * 4096.f) << 8)
                 | ((uint32_t)to_e4m3(r2 * 4096.f) << 16)
                 | ((uint32_t)to_e4m3(r3 * 4096.f) << 24);
    *(uint32_t*)(gB8 + base)      = lo8;   // [xl8' | xh8]
    *(uint32_t*)(gB8 + base + 16) = hi8;
}
__global__ void k_tsplit(const float* __restrict__ x) {
    __shared__ float t[32][33];
    int b = blockIdx.z, s0 = blockIdx.x * 32, d0 = blockIdx.y * 32;
    int tx = threadIdx.x, ty = threadIdx.y;
    const float* xb = x + (size_t)b * S * D;
#pragma unroll
    for (int i = 0; i < 32; i += 8)
        t[ty + i][tx] = xb[(size_t)(s0 + ty + i) * D + d0 + tx];
    __syncthreads();
#pragma unroll
    for (int i = 0; i < 32; i += 8) {
        int dr = ty + i;
        float v = t[tx][dr];
        __half h = __float2half(v);
        __half l = __float2half(v - __half2float(h));
        size_t o = ((size_t)b * D + d0 + dr) * S + s0 + tx;
        gVh[o] = h; gVl[o] = l;
    }
}

// ---------------- K1: scores + per-tile softmax stats -----------------------
// 16 warps 4(m)x4(n), warp tile 32x32, CTA tile 128x128, k-chunk 32
__global__ void __launch_bounds__(512) k1(float* __restrict__ sc)
{
    extern __shared__ __align__(128) char smem[];
    const uint32_t sb = smem_u32(smem);
    const int tid = threadIdx.x, lane = tid & 31, warp = tid >> 5;
    const int wm = warp & 3, wn = warp >> 2;
    const int bb = blockIdx.z, lt = blockIdx.y, st = blockIdx.x;
    const int l0 = lt * 128, s0 = st * 128;

    // lane-derived ldsm address pieces
    const int lr16 = lane & 15, lk16 = lane >> 4;       // fp16 A
    const int m8 = lane >> 3, rin = lane & 7;           // fp8 / fp16-B matrix id

    float acc16[2][4][4], acc8[2][4][4];
#pragma unroll
    for (int i = 0; i < 2; i++)
#pragma unroll
        for (int j = 0; j < 4; j++)
#pragma unroll
            for (int e = 0; e < 4; e++) { acc16[i][j][e] = 0.f; acc8[i][j][e] = 0.f; }

    auto stage_c = [&](int c) {
        uint32_t base = sb + HDR + (c % 3) * STAGE1;
        int kc = c * 32;
        int r = tid >> 2, q = tid & 3;
        uint32_t so = r * PITCH + q * 16;
        // A (U) rows, guarded
        int l = l0 + r;
        int lc = l < L ? l : L - 1;
        uint32_t sz = (l < L) ? 16u : 0u;
        cp16(base + OFF_AH + so, gUh + (size_t)lc * D + kc + q * 8, sz);
        cp16(base + OFF_A8 + so, gA8 + (size_t)lc * (D * 2) + c * 64 + q * 16, sz);
        // B (x) rows
        size_t xr = (size_t)bb * S + s0 + r;
        cp16(base + OFF_BH + so, gXh + xr * D + kc + q * 8, 16);
        cp16(base + OFF_B8 + so, gB8 + xr * (D * 2) + c * 64 + q * 16, 16);
        cp_commit();
    };

    stage_c(0);
    stage_c(1);

    constexpr int NC = 8;
    for (int c = 0; c < NC; c++) {
        if (c < NC - 1) cp_wait<1>(); else cp_wait<0>();
        __syncthreads();
        if (c + 2 < NC) stage_c(c + 2);
        uint32_t base = sb + HDR + (c % 3) * STAGE1;

        // ---- fp16 hh term ----
#pragma unroll
        for (int ks = 0; ks < 2; ks++) {
            uint32_t Ah[2][4];
#pragma unroll
            for (int mt = 0; mt < 2; mt++)
                ldsm4(Ah[mt], base + OFF_AH
                      + (wm * 32 + mt * 16 + lr16) * PITCH + lk16 * 16 + ks * 32);
#pragma unroll
            for (int g = 0; g < 2; g++) {
                uint32_t Bh[4];
                ldsm4(Bh, base + OFF_BH
                      + (wn * 32 + g * 16 + rin + ((lane >> 4) & 1) * 8) * PITCH
                      + ((lane >> 3) & 1) * 16 + ks * 32);
#pragma unroll
                for (int mt = 0; mt < 2; mt++) {
                    mma_f16(acc16[mt][g * 2],     Ah[mt], Bh[0], Bh[1]);
                    mma_f16(acc16[mt][g * 2 + 1], Ah[mt], Bh[2], Bh[3]);
                }
            }
        }
        // ---- fp8 cross term (both cross products, K-packed) ----
        {
            uint32_t A8f[2][4];
#pragma unroll
            for (int mt = 0; mt < 2; mt++)
                ldsm4(A8f[mt], base + OFF_A8
                      + (wm * 32 + mt * 16 + (m8 & 1) * 8 + rin) * PITCH
                      + (m8 >> 1) * 16);
#pragma unroll
            for (int g = 0; g < 2; g++) {
                uint32_t B8f[4];
                ldsm4(B8f, base + OFF_B8
                      + (wn * 32 + g * 16 + (m8 >> 1) * 8 + rin) * PITCH
                      + (m8 & 1) * 16);
#pragma unroll
                for (int mt = 0; mt < 2; mt++) {
                    mma_fp8(acc8[mt][g * 2],     A8f[mt], B8f[0], B8f[1]);
                    mma_fp8(acc8[mt][g * 2 + 1], A8f[mt], B8f[2], B8f[3]);
                }
            }
        }
    }

    // combine terms
#pragma unroll
    for (int mt = 0; mt < 2; mt++)
#pragma unroll
        for (int j = 0; j < 4; j++)
#pragma unroll
            for (int e = 0; e < 4; e++)
                acc16[mt][j][e] += acc8[mt][j][e] * SC8;

    // ---- epilogue: stats + staged coalesced score stores ----
    float* spmax = (float*)smem;          // [4][128]
    float* spz   = spmax + 512;           // [4][128]
    float* srow  = spz + 512;             // [128]
    float* Cs    = (float*)(smem + HDR);  // [128][LDC]
    const int rbase = wm * 32 + (lane >> 2);

#pragma unroll
    for (int mt = 0; mt < 2; mt++)
#pragma unroll
        for (int h = 0; h < 2; h++) {
            float m = -3.4e38f;
#pragma unroll
            for (int j = 0; j < 4; j++)
                m = fmaxf(m, fmaxf(acc16[mt][j][h*2], acc16[mt][j][h*2+1]));
            m = fmaxf(m, __shfl_xor_sync(0xffffffffu, m, 1));
            m = fmaxf(m, __shfl_xor_sync(0xffffffffu, m, 2));
            if ((lane & 3) == 0)
                spmax[wn * 128 + rbase + mt * 16 + h * 8] = m;
        }
    __syncthreads();
    if (tid < 128) {
        float m = fmaxf(fmaxf(spmax[tid], spmax[128 + tid]),
                        fmaxf(spmax[256 + tid], spmax[384 + tid]));
        srow[tid] = m;
    }
    __syncthreads();
#pragma unroll
    for (int mt = 0; mt < 2; mt++) {
        const int r = wm * 32 + mt * 16 + (lane >> 2);
        const int ccol = wn * 32 + (lane & 3) * 2;
#pragma unroll
        for (int h = 0; h < 2; h++) {
            float M = srow[rbase + mt * 16 + h * 8];
            float z = 0.f;
#pragma unroll
            for (int j = 0; j < 4; j++)
                z += __expf(acc16[mt][j][h*2] - M) + __expf(acc16[mt][j][h*2+1] - M);
            z += __shfl_xor_sync(0xffffffffu, z, 1);
            z += __shfl_xor_sync(0xffffffffu, z, 2);
            if ((lane & 3) == 0)
                spz[wn * 128 + rbase + mt * 16 + h * 8] = z;
        }
#pragma unroll
        for (int j = 0; j < 4; j++) {
            *(float2*)&Cs[(size_t)r * LDC + ccol + j * 8] =
                make_float2(acc16[mt][j][0], acc16[mt][j][1]);
            *(float2*)&Cs[(size_t)(r + 8) * LDC + ccol + j * 8] =
                make_float2(acc16[mt][j][2], acc16[mt][j][3]);
        }
    }
    __syncthreads();
    if (tid < 128) {
        int l = l0 + tid;
        if (l < L) {
            size_t p = ((size_t)bb * L + l) * NST + st;
            g_pm[p] = srow[tid];
            g_pz[p] = spz[tid] + spz[128 + tid] + spz[256 + tid] + spz[384 + tid];
        }
    }
#pragma unroll
    for (int t = 0; t < 8; t++) {
        int idx = t * 512 + tid;
        int row = idx >> 5, c4 = idx & 31;
        int l = l0 + row;
        if (l < L)
            *(float4*)(sc + ((size_t)bb * L + l) * S + s0 + c4 * 4) =
                *(const float4*)&Cs[(size_t)row * LDC + c4 * 4];
    }
}

// ---------------- K2: reduce partial stats ----------------------------------
__global__ void k_reduce() {
    int idx = blockIdx.x * blockDim.x + threadIdx.x;
    if (idx >= B * L) return;
    const float* pm = g_pm + (size_t)idx * NST;
    const float* pz = g_pz + (size_t)idx * NST;
    float M = -3.4e38f;
#pragma unroll
    for (int t = 0; t < NST; t++) M = fmaxf(M, pm[t]);
    float Z = 0.f;
#pragma unroll
    for (int t = 0; t < NST; t++) Z += pz[t] * __expf(pm[t] - M);
    g_M[idx]  = M;
    g_Zi[idx] = 1.0f / Z;
}

// ---------------- K3: alpha (final) + out = alpha @ x, fp16 2-term ----------
struct MmaCtx { uint32_t arow, brow; };
__device__ __forceinline__ MmaCtx make_ctx(int warp, int lane) {
    int wm = warp & 3, wn = warp >> 2;
    MmaCtx c;
    c.arow = (uint32_t)((wm * 32 + (lane & 15)) * PITCH + (lane >> 4) * 16);
    c.brow = (uint32_t)((wn * 64 + (lane & 7) + ((lane >> 4) & 1) * 8) * PITCH
                        + ((lane >> 3) & 1) * 16);
    return c;
}

__device__ __forceinline__ void tile_mma3(uint32_t base, const MmaCtx& cx,
                                          float (&acc)[2][8][4])
{
#pragma unroll
    for (int ks = 0; ks < 2; ks++) {
        uint32_t Ah[2][4];
#pragma unroll
        for (int mt = 0; mt < 2; mt++)
            ldsm4(Ah[mt], base + ST3_A + cx.arow + mt * (16 * PITCH) + ks * 32);
#pragma unroll
        for (int nph = 0; nph < 2; nph++) {
            uint32_t Bh[2][4], Bl[2][4];
#pragma unroll
            for (int j = 0; j < 2; j++) {
                int np = nph * 2 + j;
                ldsm4(Bh[j], base + ST3_BH + cx.brow + np * (16 * PITCH) + ks * 32);
                ldsm4(Bl[j], base + ST3_BL + cx.brow + np * (16 * PITCH) + ks * 32);
            }
#pragma unroll
            for (int j = 0; j < 2; j++) {
                int np = nph * 2 + j;
#pragma unroll
                for (int mt = 0; mt < 2; mt++) {
                    mma_f16(acc[mt][np*2],   Ah[mt], Bh[j][0], Bh[j][1]);
                    mma_f16(acc[mt][np*2+1], Ah[mt], Bh[j][2], Bh[j][3]);
                }
            }
#pragma unroll
            for (int j = 0; j < 2; j++) {
                int np = nph * 2 + j;
#pragma unroll
                for (int mt = 0; mt < 2; mt++) {
                    mma_f16(acc[mt][np*2],   Ah[mt], Bl[j][0], Bl[j][1]);
                    mma_f16(acc[mt][np*2+1], Ah[mt], Bl[j][2], Bl[j][3]);
                }
            }
        }
    }
}

__global__ void __launch_bounds__(512) k3(float* __restrict__ alpha,
                                          float* __restrict__ out)
{
    extern __shared__ __align__(128) char smem[];
    const uint32_t sb = smem_u32(smem);
    const int tid = threadIdx.x, lane = tid & 31, warp = tid >> 5;
    const int wm = warp & 3, wn = warp >> 2;
    const int bb = blockIdx.y, lt = blockIdx.x, l0 = lt * 128;
    const MmaCtx cx = make_ctx(warp, lane);

    float* Ms = (float*)smem;         // [128]
    float* Zs = Ms + 128;             // [128]
    if (tid < 128) {
        int l = l0 + tid;
        Ms[tid] = (l < L) ? g_M [(size_t)bb * L + l] : 0.f;
        Zs[tid] = (l < L) ? g_Zi[(size_t)bb * L + l] : 0.f;
    }
    __syncthreads();

    float acc[2][8][4];
#pragma unroll
    for (int i = 0; i < 2; i++)
#pragma unroll
        for (int j = 0; j < 8; j++)
#pragma unroll
            for (int k = 0; k < 4; k++) acc[i][j][k] = 0.f;

    const int ar = tid >> 3, ac = tid & 7;

    auto stage_b = [&](int c) {
        uint32_t base = sb + HDR + (c % 3) * STAGE3;
        int s0 = c * 32;
#pragma unroll
        for (int t = 0; t < 2; t++) {
            int idx = t * 512 + tid;
            int r = idx >> 2, c16 = idx & 3;
            size_t g = ((size_t)bb * D + r) * S + s0 + c16 * 8;
            uint32_t so = r * PITCH + c16 * 16;
            cp16(base + ST3_BH + so, gVh + g, 16);
            cp16(base + ST3_BL + so, gVl + g, 16);
        }
        cp_commit();
    };
    auto a_load = [&](int c, float4* v) {
        int s0 = c * 32;
#pragma unroll
        for (int t = 0; t < 2; t++) {
            int l = l0 + ar + t * 64;
            v[t] = (l < L)
                 ? *(const float4*)(alpha + ((size_t)bb * L + l) * S + s0 + ac * 4)
                 : make_float4(0,0,0,0);
        }
    };
    auto a_store = [&](int c, const float4* v) {
        int s0 = c * 32;
        uint32_t base = (uint32_t)(HDR + (c % 3) * STAGE3);
#pragma unroll
        for (int t = 0; t < 2; t++) {
            int r = ar + t * 64;
            int l = l0 + r;
            float4 a = v[t];
            float M = Ms[r], Z = Zs[r];
            a.x = __expf(a.x - M) * Z;
            a.y = __expf(a.y - M) * Z;
            a.z = __expf(a.z - M) * Z;
            a.w = __expf(a.w - M) * Z;
            if (l >= L) a = make_float4(0,0,0,0);
            else
                *(float4*)(alpha + ((size_t)bb * L + l) * S + s0 + ac * 4) = a;
            uint32_t so = r * PITCH + ac * 8;
            *(uint2*)(smem + base + ST3_A + so) =
                make_uint2(packh2(a.x, a.y), packh2(a.z, a.w));
        }
    };

    float4 v0[2], v1[2];
    stage_b(0); a_load(0, v0); a_store(0, v0);
    stage_b(1); a_load(1, v1); a_store(1, v1);

    constexpr int NC = 128;
    float4 vp[2];
    for (int c = 0; c < NC; c++) {
        if (c < NC - 1) cp_wait<1>(); else cp_wait<0>();
        __syncthreads();
        bool pf = (c + 2 < NC);
        if (pf) { stage_b(c + 2); a_load(c + 2, vp); }
        tile_mma3(sb + HDR + (c % 3) * STAGE3, cx, acc);
        if (pf) a_store(c + 2, vp);
    }

    // ---- epilogue: stage C, coalesced out stores ----
    __syncthreads();
    float* Cs = (float*)(smem + HDR);  // [128][LDC3]
#pragma unroll
    for (int mt = 0; mt < 2; mt++) {
        const int r = wm * 32 + mt * 16 + (lane >> 2);
        const int ccol = wn * 64 + (lane & 3) * 2;
#pragma unroll
        for (int nt = 0; nt < 8; nt++) {
            *(float2*)&Cs[(size_t)r * LDC3 + ccol + nt * 8] =
                make_float2(acc[mt][nt][0], acc[mt][nt][1]);
            *(float2*)&Cs[(size_t)(r + 8) * LDC3 + ccol + nt * 8] =
                make_float2(acc[mt][nt][2], acc[mt][nt][3]);
        }
    }
    __syncthreads();
#pragma unroll
    for (int t = 0; t < 16; t++) {
        int idx = t * 512 + tid;
        int row = idx >> 6, c4 = idx & 63;
        int l = l0 + row;
        if (l < L)
            *(float4*)(out + ((size_t)bb * L + l) * D + c4 * 4) =
                *(const float4*)&Cs[(size_t)row * LDC3 + c4 * 4];
    }
}

// ---------------------------------------------------------------------------
extern "C" void kernel_launch(void* const* d_in, const int* in_sizes, int n_in,
                              void* d_out, int out_size)
{
    const float* x = (const float*)d_in[0];   // [B,S,D]
    const float* U = (const float*)d_in[1];   // [L,D]

    float* out_ptr   = (float*)d_out;                      // [B,L,D]
    float* alpha_ptr = (float*)d_out + (size_t)B * L * D;  // [B,L,S]

    cudaFuncSetAttribute(k1, cudaFuncAttributeMaxDynamicSharedMemorySize, SMEM1);
    cudaFuncSetAttribute(k3, cudaFuncAttributeMaxDynamicSharedMemorySize, SMEM3);

    k_split_u<<<(L * D / 4 + 255) / 256, 256>>>(U);
    k_splitx<<<(B * S * D / 4 + 255) / 256, 256>>>(x);
    k_tsplit<<<dim3(S / 32, D / 32, B), dim3(32, 8)>>>(x);

    k1<<<dim3(NST, NLT, B), 512, SMEM1>>>(alpha_ptr);

    k_reduce<<<(B * L + 255) / 256, 256>>>();

    k3<<<dim3(NLT, B), 512, SMEM3>>>(alpha_ptr, out_ptr);
}